// round 1
// baseline (speedup 1.0000x reference)
#include <cuda_runtime.h>

// SwitchLinear: out[t] = (W[route[t]] + Wf) @ x[t] + bias[route[t]] + bias_fact
// B=4096 tokens, IN=OUT=256, E=16, fp32.
//
// Strategy: group tokens by expert (grouped GEMM).
//  Kernel A: warp-aggregated histogram + scatter -> sorted token ids + tile table.
//  Kernel B: one block per (expert, 32-token tile): 32x256x256 fp32 GEMM,
//            K-chunked through conflict-free shared memory, prefetch-pipelined.

#define B_TOK   4096
#define E_NUM   16
#define IN_DIM  256
#define OUT_DIM 256
#define TILE_T  32
#define KC      32
#define MAX_TILES 160          // true max tiles = 4096/32 + 16 = 144
#define GRID_B  144
#define THREADS_B 256
#define W_STRIDE 257           // 256 + 1 pad: STS/LDS conflict-free (scalar access)
#define I_STRIDE 33            // 32 + 1 pad

__device__ int g_sorted[B_TOK];
__device__ int g_tile_e[MAX_TILES];
__device__ int g_tile_base[MAX_TILES];
__device__ int g_tile_cnt[MAX_TILES];
__device__ int g_ntiles;

// ---------------------------------------------------------------------------
// Kernel A: bucket tokens by expert, build tile table.
// ---------------------------------------------------------------------------
__global__ void build_tiles_kernel(const int* __restrict__ route) {
    __shared__ int cnt[E_NUM];
    __shared__ int cur[E_NUM];
    const int tid  = threadIdx.x;
    const int lane = tid & 31;

    if (tid < E_NUM) cnt[tid] = 0;
    __syncthreads();

    // warp-aggregated histogram
    for (int t = tid; t < B_TOK; t += blockDim.x) {
        int e = route[t];
        unsigned m = __match_any_sync(0xffffffffu, e);
        int leader = __ffs(m) - 1;
        if (lane == leader) atomicAdd(&cnt[e], __popc(m));
    }
    __syncthreads();

    if (tid == 0) {
        int s = 0, nt = 0;
        for (int e = 0; e < E_NUM; e++) {
            cur[e] = s;
            int c = cnt[e];
            for (int j = 0; j < c; j += TILE_T) {
                g_tile_e[nt]    = e;
                g_tile_base[nt] = s + j;
                g_tile_cnt[nt]  = (c - j < TILE_T) ? (c - j) : TILE_T;
                nt++;
            }
            s += c;
        }
        g_ntiles = nt;
    }
    __syncthreads();

    // warp-aggregated scatter
    for (int t = tid; t < B_TOK; t += blockDim.x) {
        int e = route[t];
        unsigned m = __match_any_sync(0xffffffffu, e);
        int leader = __ffs(m) - 1;
        int rank = __popc(m & ((1u << lane) - 1u));
        int base = 0;
        if (lane == leader) base = atomicAdd(&cur[e], __popc(m));
        base = __shfl_sync(m, base, leader);
        g_sorted[base + rank] = t;
    }
}

// ---------------------------------------------------------------------------
// Kernel B: grouped GEMM tile. 256 threads.
// Thread layout: og = tid&31 (output group, outs = og + 32*j, j=0..7)
//                tg = tid>>5 (token group, tokens = tg*4 + tt, tt=0..3)
// Per thread: 4 tokens x 8 outputs = 32 accumulators.
// Per k: 4 broadcast input LDS + 8 conflict-free weight LDS + 32 FFMA
//        -> FMA-pipe bound (64 FMA-lanes/cyc/SM), LDS at ~50% of port.
// ---------------------------------------------------------------------------
__global__ __launch_bounds__(THREADS_B, 1)
void switch_gemm_kernel(const float* __restrict__ input,
                        const float* __restrict__ weight,
                        const float* __restrict__ wfact,
                        const float* __restrict__ bias,
                        const float* __restrict__ bfact,
                        float* __restrict__ out) {
    const int bid = blockIdx.x;
    if (bid >= g_ntiles) return;

    const int tid   = threadIdx.x;
    const int e     = g_tile_e[bid];
    const int tbase = g_tile_base[bid];
    const int tcnt  = g_tile_cnt[bid];

    __shared__ float w_s[KC][W_STRIDE];
    __shared__ float in_s[KC][I_STRIDE];
    __shared__ int   toks[TILE_T];

    if (tid < TILE_T) {
        int i = (tid < tcnt) ? tid : (tcnt - 1);   // pad with last valid token
        toks[tid] = g_sorted[tbase + i];
    }
    __syncthreads();

    const int og = tid & 31;
    const int tg = tid >> 5;

    float acc[4][8];
#pragma unroll
    for (int tt = 0; tt < 4; tt++)
#pragma unroll
        for (int j = 0; j < 8; j++) acc[tt][j] = 0.0f;

    const float* __restrict__ wexp = weight + (size_t)e * (OUT_DIM * IN_DIM);

    // load assignment for staging:
    //   weight: idx = tid + 256*it (it=0..7): o = idx>>3 (0..255), k4 = idx&7
    //   input:  t = tid>>3 (0..31), k4 = tid&7
    const int ld_t  = tid >> 3;
    const int ld_k4 = tid & 7;
    const int my_tok_row = toks[ld_t] * IN_DIM;

    float4 wreg[8];
    float4 ireg;

    // prefetch chunk 0
    {
        const int kc = 0;
#pragma unroll
        for (int it = 0; it < 8; it++) {
            int idx = tid + THREADS_B * it;
            int o = idx >> 3, k4 = idx & 7;
            float4 w4 = *(const float4*)(wexp  + o * IN_DIM + kc + k4 * 4);
            float4 f4 = *(const float4*)(wfact + o * IN_DIM + kc + k4 * 4);
            wreg[it].x = w4.x + f4.x;
            wreg[it].y = w4.y + f4.y;
            wreg[it].z = w4.z + f4.z;
            wreg[it].w = w4.w + f4.w;
        }
        ireg = *(const float4*)(input + my_tok_row + kc + ld_k4 * 4);
    }

    for (int kc = 0; kc < IN_DIM; kc += KC) {
        // store staged chunk to smem (conflict-free: banks (4*k4+c+o)%32 distinct)
#pragma unroll
        for (int it = 0; it < 8; it++) {
            int idx = tid + THREADS_B * it;
            int o = idx >> 3, k4 = idx & 7;
            w_s[k4 * 4 + 0][o] = wreg[it].x;
            w_s[k4 * 4 + 1][o] = wreg[it].y;
            w_s[k4 * 4 + 2][o] = wreg[it].z;
            w_s[k4 * 4 + 3][o] = wreg[it].w;
        }
        in_s[ld_k4 * 4 + 0][ld_t] = ireg.x;
        in_s[ld_k4 * 4 + 1][ld_t] = ireg.y;
        in_s[ld_k4 * 4 + 2][ld_t] = ireg.z;
        in_s[ld_k4 * 4 + 3][ld_t] = ireg.w;
        __syncthreads();

        // prefetch next chunk (LDGs in flight under the compute below)
        const int kn = kc + KC;
        if (kn < IN_DIM) {
#pragma unroll
            for (int it = 0; it < 8; it++) {
                int idx = tid + THREADS_B * it;
                int o = idx >> 3, k4 = idx & 7;
                float4 w4 = *(const float4*)(wexp  + o * IN_DIM + kn + k4 * 4);
                float4 f4 = *(const float4*)(wfact + o * IN_DIM + kn + k4 * 4);
                wreg[it].x = w4.x + f4.x;
                wreg[it].y = w4.y + f4.y;
                wreg[it].z = w4.z + f4.z;
                wreg[it].w = w4.w + f4.w;
            }
            ireg = *(const float4*)(input + my_tok_row + kn + ld_k4 * 4);
        }

        // compute: per k, 4 input broadcasts + 8 conflict-free weight loads + 32 FFMA
#pragma unroll
        for (int k = 0; k < KC; k++) {
            float a0 = in_s[k][tg * 4 + 0];
            float a1 = in_s[k][tg * 4 + 1];
            float a2 = in_s[k][tg * 4 + 2];
            float a3 = in_s[k][tg * 4 + 3];
            float b[8];
#pragma unroll
            for (int j = 0; j < 8; j++) b[j] = w_s[k][og + 32 * j];
#pragma unroll
            for (int j = 0; j < 8; j++) {
                acc[0][j] += a0 * b[j];
                acc[1][j] += a1 * b[j];
                acc[2][j] += a2 * b[j];
                acc[3][j] += a3 * b[j];
            }
        }
        __syncthreads();
    }

    // epilogue: bias + store (coalesced: warp covers og 0..31 per j)
    float bsum[8];
#pragma unroll
    for (int j = 0; j < 8; j++)
        bsum[j] = bias[e * OUT_DIM + og + 32 * j] + bfact[og + 32 * j];

#pragma unroll
    for (int tt = 0; tt < 4; tt++) {
        int t = tg * 4 + tt;
        if (t < tcnt) {
            int tok = toks[t];
#pragma unroll
            for (int j = 0; j < 8; j++)
                out[tok * OUT_DIM + og + 32 * j] = acc[tt][j] + bsum[j];
        }
    }
}

// ---------------------------------------------------------------------------
extern "C" void kernel_launch(void* const* d_in, const int* in_sizes, int n_in,
                              void* d_out, int out_size) {
    const float* input  = (const float*)d_in[0];
    const int*   route  = (const int*)d_in[1];
    const float* weight = (const float*)d_in[2];
    const float* wfact  = (const float*)d_in[3];
    const float* bias   = (const float*)d_in[4];
    const float* bfact  = (const float*)d_in[5];
    float* out = (float*)d_out;

    build_tiles_kernel<<<1, 256>>>(route);
    switch_gemm_kernel<<<GRID_B, THREADS_B>>>(input, weight, wfact, bias, bfact, out);
}